// round 3
// baseline (speedup 1.0000x reference)
#include <cuda_runtime.h>

#define B_DIM 256
#define T_DIM 64
#define D_DIM 2048
#define THRESHOLD 0.99f
#define EPSILON 0.01f

#define THREADS 128
#define D4 (D_DIM / 4)                    // 512 float4 per row
#define BLOCKS_PER_B (D4 / THREADS)       // 4
#define SPLIT 2
#define T_PER_SPLIT (T_DIM / SPLIT)       // 32
#define TBATCH 4

// Partial-sum scratch: [SPLIT][B][D] fp32 = 4 MB (static __device__, allowed).
__device__ float g_partial[SPLIT * B_DIM * D_DIM];

// ---------------------------------------------------------------------------
// Kernel A: weighted partial reduction over one T-half.
// grid = B * BLOCKS_PER_B * SPLIT, block = 128.
// Each block recomputes halting weights (cheap) then reduces 32 t-steps of
// its 128-float4 column strip into g_partial. (chunk==0 && split==0) blocks
// also emit weights + ponder_cost.
// ---------------------------------------------------------------------------
__global__ __launch_bounds__(THREADS, 12)
void act_partial_kernel(const float* __restrict__ halt_probs,   // [B,T]
                        const float* __restrict__ outputs,      // [B,T,D]
                        const float* __restrict__ step_weights, // [B,T]
                        float* __restrict__ out_ponder,         // [B]
                        float* __restrict__ out_weights)        // [B,T]
{
    const int bid   = blockIdx.x;
    const int split = bid % SPLIT;
    const int chunk = (bid / SPLIT) % BLOCKS_PER_B;
    const int b     = bid / (SPLIT * BLOCKS_PER_B);
    const int tid   = threadIdx.x;

    __shared__ float sp[T_DIM];
    __shared__ float wsh[T_DIM];
    __shared__ int   s_h;
    __shared__ float s_rem;
    __shared__ float s_wsum;

    // ---- halting weights for batch b ----
    if (tid < T_DIM) sp[tid] = halt_probs[b * T_DIM + tid];
    __syncthreads();

    if (tid == 0) {
        float cum = 0.0f;
        int   h   = T_DIM - 1;
        bool  found = false;
        #pragma unroll
        for (int i = 0; i < T_DIM; i++) {
            cum += sp[i];
            if (!found && cum >= THRESHOLD) { found = true; h = i; }
        }
        float cum_at = 0.0f;
        for (int i = 0; i <= h; i++) cum_at += sp[i];
        s_h   = h;
        s_rem = 1.0f - cum_at + sp[h];
    }
    __syncthreads();

    const int   h   = s_h;
    const float rem = s_rem;

    if (tid < T_DIM) {
        float w = (tid < h) ? sp[tid] : ((tid == h) ? rem : 0.0f);
        w *= step_weights[b * T_DIM + tid];
        wsh[tid] = w;
    }
    __syncthreads();

    if (tid == 0) {
        float s = 0.0f;
        #pragma unroll
        for (int i = 0; i < T_DIM; i++) s += wsh[i];
        s_wsum = fmaxf(s, EPSILON);
    }
    __syncthreads();

    const float inv_wsum = 1.0f / s_wsum;
    if (tid < T_DIM) wsh[tid] *= inv_wsum;
    __syncthreads();

    if (chunk == 0 && split == 0) {
        if (tid < T_DIM) out_weights[b * T_DIM + tid] = wsh[tid];
        if (tid == 0) {
            float pc = 0.0f;
            #pragma unroll
            for (int i = 0; i < T_DIM; i++) pc += wsh[i] * (float)(i + 1);
            out_ponder[b] = pc;
        }
    }

    // ---- weighted partial reduction over this split's 32 t-steps ----
    const int d4     = chunk * THREADS + tid;          // float4 col in [0, D4)
    const int t_base = split * T_PER_SPLIT;

    const float4* __restrict__ base =
        reinterpret_cast<const float4*>(outputs)
        + (size_t)b * T_DIM * D4 + (size_t)t_base * D4 + d4;

    float4 acc = make_float4(0.f, 0.f, 0.f, 0.f);

    #pragma unroll 1
    for (int t0 = 0; t0 < T_PER_SPLIT; t0 += TBATCH) {
        float4 v0 = base[(size_t)(t0 + 0) * D4];
        float4 v1 = base[(size_t)(t0 + 1) * D4];
        float4 v2 = base[(size_t)(t0 + 2) * D4];
        float4 v3 = base[(size_t)(t0 + 3) * D4];

        const float w0 = wsh[t_base + t0 + 0];
        const float w1 = wsh[t_base + t0 + 1];
        const float w2 = wsh[t_base + t0 + 2];
        const float w3 = wsh[t_base + t0 + 3];

        acc.x = fmaf(w0, v0.x, acc.x); acc.y = fmaf(w0, v0.y, acc.y);
        acc.z = fmaf(w0, v0.z, acc.z); acc.w = fmaf(w0, v0.w, acc.w);
        acc.x = fmaf(w1, v1.x, acc.x); acc.y = fmaf(w1, v1.y, acc.y);
        acc.z = fmaf(w1, v1.z, acc.z); acc.w = fmaf(w1, v1.w, acc.w);
        acc.x = fmaf(w2, v2.x, acc.x); acc.y = fmaf(w2, v2.y, acc.y);
        acc.z = fmaf(w2, v2.z, acc.z); acc.w = fmaf(w2, v2.w, acc.w);
        acc.x = fmaf(w3, v3.x, acc.x); acc.y = fmaf(w3, v3.y, acc.y);
        acc.z = fmaf(w3, v3.z, acc.z); acc.w = fmaf(w3, v3.w, acc.w);
    }

    float4* part = reinterpret_cast<float4*>(g_partial)
                   + (size_t)split * B_DIM * D4 + (size_t)b * D4 + d4;
    *part = acc;
}

// ---------------------------------------------------------------------------
// Kernel B: combine the SPLIT partials into final_out.
// grid = B*D4/256 = 512 blocks of 256 threads, one float4 each.
// ---------------------------------------------------------------------------
__global__ __launch_bounds__(256)
void act_combine_kernel(float* __restrict__ final_out)  // [B,D]
{
    const size_t i = (size_t)blockIdx.x * 256 + threadIdx.x;  // float4 index
    const float4* p0 = reinterpret_cast<const float4*>(g_partial) + i;
    const float4* p1 = reinterpret_cast<const float4*>(g_partial)
                       + (size_t)B_DIM * D4 + i;
    float4 a = *p0;
    float4 b = *p1;
    a.x += b.x; a.y += b.y; a.z += b.z; a.w += b.w;
    reinterpret_cast<float4*>(final_out)[i] = a;
}

// ---------------------------------------------------------------------------
// kernel_launch
// Inputs: halt_probs [B,T,1], outputs [B,T,D], step_weights [B,T]  (fp32)
// Output: concat(final_output [B*D], ponder_cost [B], weights [B*T]) fp32
// ---------------------------------------------------------------------------
extern "C" void kernel_launch(void* const* d_in, const int* in_sizes, int n_in,
                              void* d_out, int out_size)
{
    const float* halt_probs   = (const float*)d_in[0];
    const float* outputs      = (const float*)d_in[1];
    const float* step_weights = (const float*)d_in[2];

    float* out         = (float*)d_out;
    float* final_out   = out;                              // [B,D]
    float* ponder_out  = out + (size_t)B_DIM * D_DIM;      // [B]
    float* weights_out = ponder_out + B_DIM;               // [B,T]

    act_partial_kernel<<<B_DIM * BLOCKS_PER_B * SPLIT, THREADS>>>(
        halt_probs, outputs, step_weights, ponder_out, weights_out);

    act_combine_kernel<<<(B_DIM * D4) / 256, 256>>>(final_out);
}

// round 4
// speedup vs baseline: 1.3074x; 1.3074x over previous
#include <cuda_runtime.h>

#define B_DIM 256
#define T_DIM 64
#define D_DIM 2048
#define THRESHOLD 0.99f
#define EPSILON 0.01f

#define THREADS 256
#define HALF_THREADS 128
#define D4 (D_DIM / 4)                    // 512 float4 per row
#define BLOCKS_PER_B (D4 / HALF_THREADS)  // 4
#define T_HALF (T_DIM / 2)                // 32
#define TBATCH 4

// ---------------------------------------------------------------------------
// Fused kernel, block-internal T-split.
// grid = B*4, block = 256.
//   threads [0,128)  : reduce t in [0,32)  over 128 float4 columns
//   threads [128,256): reduce t in [32,64) over the same 128 columns
// Halves combine through shared memory; one float4 store per column.
// Prologue recomputes halting weights per block (cheap, T=64).
// ---------------------------------------------------------------------------
__global__ __launch_bounds__(THREADS)
void act_fused_kernel(const float* __restrict__ halt_probs,   // [B,T]
                      const float* __restrict__ outputs,      // [B,T,D]
                      const float* __restrict__ step_weights, // [B,T]
                      float* __restrict__ final_out,          // [B,D]
                      float* __restrict__ out_ponder,         // [B]
                      float* __restrict__ out_weights)        // [B,T]
{
    const int b     = blockIdx.x / BLOCKS_PER_B;
    const int chunk = blockIdx.x % BLOCKS_PER_B;
    const int tid   = threadIdx.x;
    const int half  = tid >> 7;          // 0 or 1
    const int lane  = tid & (HALF_THREADS - 1);

    __shared__ float  sp[T_DIM];
    __shared__ float  wsh[T_DIM];
    __shared__ int    s_h;
    __shared__ float  s_rem;
    __shared__ float  s_wsum;
    __shared__ float4 s_part[HALF_THREADS];   // 2 KB

    // ---- prologue: halting weights for batch b ----
    if (tid < T_DIM) sp[tid] = halt_probs[b * T_DIM + tid];
    __syncthreads();

    if (tid == 0) {
        float cum = 0.0f;
        int   h   = T_DIM - 1;
        bool  found = false;
        #pragma unroll
        for (int i = 0; i < T_DIM; i++) {
            cum += sp[i];
            if (!found && cum >= THRESHOLD) { found = true; h = i; }
        }
        float cum_at = 0.0f;
        for (int i = 0; i <= h; i++) cum_at += sp[i];
        s_h   = h;
        s_rem = 1.0f - cum_at + sp[h];
    }
    __syncthreads();

    const int   h   = s_h;
    const float rem = s_rem;

    if (tid < T_DIM) {
        float w = (tid < h) ? sp[tid] : ((tid == h) ? rem : 0.0f);
        w *= step_weights[b * T_DIM + tid];
        wsh[tid] = w;
    }
    __syncthreads();

    if (tid == 0) {
        float s = 0.0f;
        #pragma unroll
        for (int i = 0; i < T_DIM; i++) s += wsh[i];
        s_wsum = fmaxf(s, EPSILON);
    }
    __syncthreads();

    const float inv_wsum = 1.0f / s_wsum;
    if (tid < T_DIM) wsh[tid] *= inv_wsum;
    __syncthreads();

    if (chunk == 0) {
        if (tid < T_DIM) out_weights[b * T_DIM + tid] = wsh[tid];
        if (tid == 0) {
            float pc = 0.0f;
            #pragma unroll
            for (int i = 0; i < T_DIM; i++) pc += wsh[i] * (float)(i + 1);
            out_ponder[b] = pc;
        }
    }

    // ---- weighted reduction: this half's 32 t-steps, streaming loads ----
    const int d4     = chunk * HALF_THREADS + lane;   // float4 col in [0, D4)
    const int t_base = half * T_HALF;

    const float4* __restrict__ base =
        reinterpret_cast<const float4*>(outputs)
        + (size_t)b * T_DIM * D4 + (size_t)t_base * D4 + d4;

    float4 acc = make_float4(0.f, 0.f, 0.f, 0.f);

    #pragma unroll 1
    for (int t0 = 0; t0 < T_HALF; t0 += TBATCH) {
        float4 v0 = __ldcs(base + (size_t)(t0 + 0) * D4);
        float4 v1 = __ldcs(base + (size_t)(t0 + 1) * D4);
        float4 v2 = __ldcs(base + (size_t)(t0 + 2) * D4);
        float4 v3 = __ldcs(base + (size_t)(t0 + 3) * D4);

        const float w0 = wsh[t_base + t0 + 0];
        const float w1 = wsh[t_base + t0 + 1];
        const float w2 = wsh[t_base + t0 + 2];
        const float w3 = wsh[t_base + t0 + 3];

        acc.x = fmaf(w0, v0.x, acc.x); acc.y = fmaf(w0, v0.y, acc.y);
        acc.z = fmaf(w0, v0.z, acc.z); acc.w = fmaf(w0, v0.w, acc.w);
        acc.x = fmaf(w1, v1.x, acc.x); acc.y = fmaf(w1, v1.y, acc.y);
        acc.z = fmaf(w1, v1.z, acc.z); acc.w = fmaf(w1, v1.w, acc.w);
        acc.x = fmaf(w2, v2.x, acc.x); acc.y = fmaf(w2, v2.y, acc.y);
        acc.z = fmaf(w2, v2.z, acc.z); acc.w = fmaf(w2, v2.w, acc.w);
        acc.x = fmaf(w3, v3.x, acc.x); acc.y = fmaf(w3, v3.y, acc.y);
        acc.z = fmaf(w3, v3.z, acc.z); acc.w = fmaf(w3, v3.w, acc.w);
    }

    // ---- combine halves through shared, single store ----
    if (half == 1) s_part[lane] = acc;
    __syncthreads();
    if (half == 0) {
        const float4 o = s_part[lane];
        acc.x += o.x; acc.y += o.y; acc.z += o.z; acc.w += o.w;
        reinterpret_cast<float4*>(final_out)[(size_t)b * D4 + d4] = acc;
    }
}

// ---------------------------------------------------------------------------
// kernel_launch
// Inputs: halt_probs [B,T,1], outputs [B,T,D], step_weights [B,T]  (fp32)
// Output: concat(final_output [B*D], ponder_cost [B], weights [B*T]) fp32
// ---------------------------------------------------------------------------
extern "C" void kernel_launch(void* const* d_in, const int* in_sizes, int n_in,
                              void* d_out, int out_size)
{
    const float* halt_probs   = (const float*)d_in[0];
    const float* outputs      = (const float*)d_in[1];
    const float* step_weights = (const float*)d_in[2];

    float* out         = (float*)d_out;
    float* final_out   = out;                              // [B,D]
    float* ponder_out  = out + (size_t)B_DIM * D_DIM;      // [B]
    float* weights_out = ponder_out + B_DIM;               // [B,T]

    act_fused_kernel<<<B_DIM * BLOCKS_PER_B, THREADS>>>(
        halt_probs, outputs, step_weights,
        final_out, ponder_out, weights_out);
}